// round 4
// baseline (speedup 1.0000x reference)
#include <cuda_runtime.h>
#include <math.h>

// Problem dims: y_true/y_pred shape (1,1,160,192,160) fp32
#define DD 160
#define HH 192
#define WW 160
#define VOL (DD*HH*WW)          // 4,915,200
#define RAD 4                   // box window radius (win=9)
#define WSIZE 729.0f
#define INV_WSIZE (1.0f/729.0f)

// ---------------- scratch (device globals: no allocation allowed) ----------
__device__ float g_edgeI[VOL];
__device__ float g_edgeJ[VOL];
__device__ float g_shapeI[VOL];
__device__ float g_shapeJ[VOL];
__device__ float g_s1[5u * VOL];   // after w-pass: 5 channels (A, B, A2, B2, AB)
__device__ float g_s2[5u * VOL];   // after h-pass
__device__ double g_acc[3];        // per-pair sum of cc

// ---------------- accumulator reset ----------------------------------------
__global__ void k_zero_acc() {
    if (threadIdx.x < 3) g_acc[threadIdx.x] = 0.0;
}

// ---------------- 3x3x3 stencils: Laplacian + Sobel magnitude --------------
// s layout: s[dz][dy][w+1], dz/dy in {0,1,2} mapped to offsets -1..+1
__device__ __forceinline__ void stencil_eval(const float s[3][3][WW + 2], int cw,
                                             float& lap, float& shp) {
    const float m3[3] = {1.f, 2.f, 1.f};
    float c = s[1][1][cw];
    lap = 6.f * c
        - s[1][1][cw - 1] - s[1][1][cw + 1]   // w +/- 1
        - s[1][0][cw]     - s[1][2][cw]       // h +/- 1
        - s[0][1][cw]     - s[2][1][cw];      // d +/- 1

    float gx = 0.f, gy = 0.f, gz = 0.f;
    // gx: derivative along w, (1,2,1) smoothing along h, uniform along d
    #pragma unroll
    for (int dz = 0; dz < 3; dz++)
        #pragma unroll
        for (int dy = 0; dy < 3; dy++)
            gx += m3[dy] * (s[dz][dy][cw + 1] - s[dz][dy][cw - 1]);
    // gy: derivative along d, (1,2,1) smoothing along w, uniform along h
    #pragma unroll
    for (int dy = 0; dy < 3; dy++)
        #pragma unroll
        for (int dw = 0; dw < 3; dw++)
            gy += m3[dw] * (s[2][dy][cw + dw - 1] - s[0][dy][cw + dw - 1]);
    // gz: derivative along h, (1,2,1) smoothing along d, uniform along w
    #pragma unroll
    for (int dz = 0; dz < 3; dz++)
        #pragma unroll
        for (int dw = 0; dw < 3; dw++)
            gz += m3[dz] * (s[dz][2][cw + dw - 1] - s[dz][0][cw + dw - 1]);

    shp = sqrtf(gx * gx + gy * gy + gz * gz);
}

__global__ __launch_bounds__(WW) void k_deriv(const float* __restrict__ I,
                                              const float* __restrict__ J) {
    __shared__ float sI[3][3][WW + 2];
    __shared__ float sJ[3][3][WW + 2];
    const int h = blockIdx.x;
    const int d = blockIdx.y;
    const int t = threadIdx.x;

    #pragma unroll
    for (int dz = 0; dz < 3; dz++) {
        int dd = d + dz - 1;
        #pragma unroll
        for (int dy = 0; dy < 3; dy++) {
            int hh = h + dy - 1;
            bool rowok = (dd >= 0 && dd < DD && hh >= 0 && hh < HH);
            size_t rb = ((size_t)dd * HH + hh) * WW;
            for (int x = t; x < WW + 2; x += WW) {
                int ws = x - 1;
                float vi = 0.f, vj = 0.f;
                if (rowok && ws >= 0 && ws < WW) {
                    vi = __ldg(I + rb + ws);
                    vj = __ldg(J + rb + ws);
                }
                sI[dz][dy][x] = vi;
                sJ[dz][dy][x] = vj;
            }
        }
    }
    __syncthreads();

    const int cw = t + 1;
    float lapI, shpI, lapJ, shpJ;
    stencil_eval(sI, cw, lapI, shpI);
    stencil_eval(sJ, cw, lapJ, shpJ);

    size_t idx = ((size_t)d * HH + h) * WW + t;
    g_edgeI[idx]  = lapI;
    g_edgeJ[idx]  = lapJ;
    g_shapeI[idx] = shpI;
    g_shapeJ[idx] = shpJ;
}

// ---------------- pass 1: products + box sum along W ------------------------
// sel: 0 = (I,J) from args, 1 = (edgeI,edgeJ), 2 = (shapeI,shapeJ)
__global__ __launch_bounds__(WW) void k_pass_w(const float* __restrict__ Iin,
                                               const float* __restrict__ Jin,
                                               int sel) {
    __shared__ float sa[WW];
    __shared__ float sb[WW];
    const int h = blockIdx.x;
    const int d = blockIdx.y;
    const int w = threadIdx.x;
    const float* __restrict__ A = (sel == 0) ? Iin : (sel == 1) ? g_edgeI : g_shapeI;
    const float* __restrict__ B = (sel == 0) ? Jin : (sel == 1) ? g_edgeJ : g_shapeJ;

    size_t base = ((size_t)d * HH + h) * WW;
    sa[w] = A[base + w];
    sb[w] = B[base + w];
    __syncthreads();

    float s_a = 0.f, s_b = 0.f, s_aa = 0.f, s_bb = 0.f, s_ab = 0.f;
    #pragma unroll
    for (int dw = -RAD; dw <= RAD; dw++) {
        int x = w + dw;
        if (x >= 0 && x < WW) {
            float a = sa[x], b = sb[x];
            s_a += a; s_b += b;
            s_aa += a * a; s_bb += b * b; s_ab += a * b;
        }
    }
    size_t idx = base + w;
    g_s1[0u * VOL + idx] = s_a;
    g_s1[1u * VOL + idx] = s_b;
    g_s1[2u * VOL + idx] = s_aa;
    g_s1[3u * VOL + idx] = s_bb;
    g_s1[4u * VOL + idx] = s_ab;
}

// ---------------- pass 2: box sum along H -----------------------------------
// grid: (DD, 5, HCHUNKS); block: WW threads; each block does HCH h-rows.
#define HCH 48
__global__ __launch_bounds__(WW) void k_pass_h() {
    const int d = blockIdx.x;
    const int c = blockIdx.y;
    const int h0blk = blockIdx.z * HCH;
    const int w = threadIdx.x;
    const float* __restrict__ src = g_s1 + (size_t)c * VOL;
    float* __restrict__ dst = g_s2 + (size_t)c * VOL;

    for (int h = h0blk; h < h0blk + HCH; h++) {
        int h0 = h - RAD; if (h0 < 0) h0 = 0;
        int h1 = h + RAD; if (h1 > HH - 1) h1 = HH - 1;
        float s = 0.f;
        for (int hh = h0; hh <= h1; hh++)
            s += src[((size_t)d * HH + hh) * WW + w];
        dst[((size_t)d * HH + h) * WW + w] = s;
    }
}

// ---------------- pass 3: box sum along D + NCC + reduction -----------------
// grid: (HH, DCHUNKS); block: WW threads; each block does DCH d-planes.
#define DCH 20
__global__ __launch_bounds__(WW) void k_pass_d(int pair) {
    const int h = blockIdx.x;
    const int d0blk = blockIdx.y * DCH;
    const int w = threadIdx.x;

    double local = 0.0;
    for (int d = d0blk; d < d0blk + DCH; d++) {
        int d0 = d - RAD; if (d0 < 0) d0 = 0;
        int d1 = d + RAD; if (d1 > DD - 1) d1 = DD - 1;
        float Is = 0.f, Js = 0.f, I2s = 0.f, J2s = 0.f, IJs = 0.f;
        for (int dd = d0; dd <= d1; dd++) {
            size_t p = ((size_t)dd * HH + h) * WW + w;
            Is  += g_s2[0u * VOL + p];
            Js  += g_s2[1u * VOL + p];
            I2s += g_s2[2u * VOL + p];
            J2s += g_s2[3u * VOL + p];
            IJs += g_s2[4u * VOL + p];
        }
        float uI = Is * INV_WSIZE;
        float uJ = Js * INV_WSIZE;
        float cross = IJs - uJ * Is - uI * Js + uI * uJ * WSIZE;
        float Iv = I2s - 2.f * uI * Is + uI * uI * WSIZE;
        float Jv = J2s - 2.f * uJ * Js + uJ * uJ * WSIZE;
        float cc = cross * cross / (Iv * Jv + 1e-5f);
        local += (double)cc;
    }

    __shared__ double red[WW];
    red[w] = local;
    __syncthreads();
    if (w == 0) {
        double t = 0.0;
        #pragma unroll 8
        for (int i = 0; i < WW; i++) t += red[i];
        atomicAdd(&g_acc[pair], t);
    }
}

// ---------------- final combine ---------------------------------------------
__global__ void k_final(float* out) {
    // loss = 0.8*(-mean0) + 0.1*(-mean1) + 0.1*(-mean2)
    double m = (0.8 * g_acc[0] + 0.1 * g_acc[1] + 0.1 * g_acc[2]) / (double)VOL;
    out[0] = (float)(-m);
}

// ---------------- launch ----------------------------------------------------
extern "C" void kernel_launch(void* const* d_in, const int* in_sizes, int n_in,
                              void* d_out, int out_size) {
    const float* I = (const float*)d_in[0];  // y_true
    const float* J = (const float*)d_in[1];  // y_pred
    float* out = (float*)d_out;

    dim3 gridHD(HH, DD);
    dim3 gridH2(DD, 5, HH / HCH);
    dim3 gridD2(HH, DD / DCH);

    k_zero_acc<<<1, 32>>>();
    k_deriv<<<gridHD, WW>>>(I, J);

    // pair 0: original volumes
    k_pass_w<<<gridHD, WW>>>(I, J, 0);
    k_pass_h<<<gridH2, WW>>>();
    k_pass_d<<<gridD2, WW>>>(0);

    // pair 1: Laplacian edge volumes
    k_pass_w<<<gridHD, WW>>>(I, J, 1);
    k_pass_h<<<gridH2, WW>>>();
    k_pass_d<<<gridD2, WW>>>(1);

    // pair 2: Sobel-magnitude shape volumes
    k_pass_w<<<gridHD, WW>>>(I, J, 2);
    k_pass_h<<<gridH2, WW>>>();
    k_pass_d<<<gridD2, WW>>>(2);

    k_final<<<1, 1>>>(out);
}

// round 6
// speedup vs baseline: 1.7990x; 1.7990x over previous
#include <cuda_runtime.h>
#include <math.h>

// Problem dims: y_true/y_pred shape (1,1,160,192,160) fp32
#define DD 160
#define HH 192
#define WW 160
#define W4 (WW/4)               // 40 float4 per row
#define VOL (DD*HH*WW)          // 4,915,200
#define RAD 4                   // box window radius (win=9)
#define WSIZE 729.0f
#define INV_WSIZE (1.0f/729.0f)
#define NCH 15                  // 3 pairs x 5 channels (A,B,A2,B2,AB)

// ---------------- scratch (device globals: no allocation allowed) ----------
__device__ float g_s1[(size_t)NCH * VOL];   // after fused deriv+w-pass
__device__ float g_s2[(size_t)NCH * VOL];   // after h-pass
__device__ double g_acc[3];                 // per-pair sum of cc

// ---------------- small float4 helpers --------------------------------------
__device__ __forceinline__ float4 f4add(float4 a, float4 b) {
    return make_float4(a.x+b.x, a.y+b.y, a.z+b.z, a.w+b.w);
}
__device__ __forceinline__ float4 f4sub(float4 a, float4 b) {
    return make_float4(a.x-b.x, a.y-b.y, a.z-b.z, a.w-b.w);
}

// ---------------- accumulator reset ----------------------------------------
__global__ void k_zero_acc() {
    if (threadIdx.x < 3) g_acc[threadIdx.x] = 0.0;
}

// ---------------- 3x3x3 stencils: Laplacian + Sobel magnitude --------------
__device__ __forceinline__ void stencil_eval(const float s[3][3][WW + 2], int cw,
                                             float& lap, float& shp) {
    const float m3[3] = {1.f, 2.f, 1.f};
    float c = s[1][1][cw];
    lap = 6.f * c
        - s[1][1][cw - 1] - s[1][1][cw + 1]
        - s[1][0][cw]     - s[1][2][cw]
        - s[0][1][cw]     - s[2][1][cw];

    float gx = 0.f, gy = 0.f, gz = 0.f;
    #pragma unroll
    for (int dz = 0; dz < 3; dz++)
        #pragma unroll
        for (int dy = 0; dy < 3; dy++)
            gx += m3[dy] * (s[dz][dy][cw + 1] - s[dz][dy][cw - 1]);
    #pragma unroll
    for (int dy = 0; dy < 3; dy++)
        #pragma unroll
        for (int dw = 0; dw < 3; dw++)
            gy += m3[dw] * (s[2][dy][cw + dw - 1] - s[0][dy][cw + dw - 1]);
    #pragma unroll
    for (int dz = 0; dz < 3; dz++)
        #pragma unroll
        for (int dw = 0; dw < 3; dw++)
            gz += m3[dz] * (s[dz][2][cw + dw - 1] - s[dz][0][cw + dw - 1]);

    shp = sqrtf(gx * gx + gy * gy + gz * gz);
}

// ---------------- fused: deriv + products + box-sum along W -----------------
// One block per (h, d) row. Computes I,J,lap,shape per voxel, forms 15
// products, and writes the 9-tap w-box-sum of each product channel.
__global__ __launch_bounds__(WW) void k_fusedw(const float* __restrict__ I,
                                               const float* __restrict__ J) {
    __shared__ float sI[3][3][WW + 2];
    __shared__ float sJ[3][3][WW + 2];
    __shared__ float vals[6][WW];  // I, J, eI, eJ, shI, shJ (center row)
    const int h = blockIdx.x;
    const int d = blockIdx.y;
    const int t = threadIdx.x;

    #pragma unroll
    for (int dz = 0; dz < 3; dz++) {
        int dd = d + dz - 1;
        #pragma unroll
        for (int dy = 0; dy < 3; dy++) {
            int hh = h + dy - 1;
            bool rowok = (dd >= 0 && dd < DD && hh >= 0 && hh < HH);
            size_t rb = ((size_t)dd * HH + hh) * WW;
            for (int x = t; x < WW + 2; x += WW) {
                int ws = x - 1;
                float vi = 0.f, vj = 0.f;
                if (rowok && ws >= 0 && ws < WW) {
                    vi = __ldg(I + rb + ws);
                    vj = __ldg(J + rb + ws);
                }
                sI[dz][dy][x] = vi;
                sJ[dz][dy][x] = vj;
            }
        }
    }
    __syncthreads();

    const int cw = t + 1;
    float lapI, shpI, lapJ, shpJ;
    stencil_eval(sI, cw, lapI, shpI);
    stencil_eval(sJ, cw, lapJ, shpJ);
    vals[0][t] = sI[1][1][cw];
    vals[1][t] = sJ[1][1][cw];
    vals[2][t] = lapI;
    vals[3][t] = lapJ;
    vals[4][t] = shpI;
    vals[5][t] = shpJ;
    __syncthreads();

    float acc[NCH];
    #pragma unroll
    for (int c = 0; c < NCH; c++) acc[c] = 0.f;

    #pragma unroll
    for (int dw = -RAD; dw <= RAD; dw++) {
        int x = t + dw;
        if (x >= 0 && x < WW) {
            float a0 = vals[0][x], b0 = vals[1][x];
            float a1 = vals[2][x], b1 = vals[3][x];
            float a2 = vals[4][x], b2 = vals[5][x];
            acc[0] += a0;       acc[1] += b0;
            acc[2] += a0 * a0;  acc[3] += b0 * b0;  acc[4]  += a0 * b0;
            acc[5] += a1;       acc[6] += b1;
            acc[7] += a1 * a1;  acc[8] += b1 * b1;  acc[9]  += a1 * b1;
            acc[10] += a2;      acc[11] += b2;
            acc[12] += a2 * a2; acc[13] += b2 * b2; acc[14] += a2 * b2;
        }
    }

    size_t idx = ((size_t)d * HH + h) * WW + t;
    #pragma unroll
    for (int c = 0; c < NCH; c++)
        g_s1[(size_t)c * VOL + idx] = acc[c];
}

// ---------------- pass 2: sliding-window box sum along H --------------------
// thread = one float4 column of one channel of one d-plane, half the h-range.
// total threads = NCH * DD * 2 * W4 = 192000 -> 750 blocks x 256
#define HCHUNK 96
__global__ __launch_bounds__(256) void k_pass_h() {
    int tid = blockIdx.x * 256 + threadIdx.x;
    int w4 = tid % W4;  tid /= W4;
    int hc = tid % 2;   tid /= 2;
    int d  = tid % DD;  tid /= DD;
    int c  = tid;
    if (c >= NCH) return;

    size_t base = (size_t)c * VOL + (size_t)d * HH * WW;
    const float4* __restrict__ src4 = (const float4*)(g_s1 + base);
    float4* __restrict__ dst4 = (float4*)(g_s2 + base);
    const float4 z4 = make_float4(0.f, 0.f, 0.f, 0.f);

    int h0 = hc * HCHUNK;
    float4 s = z4;
    #pragma unroll
    for (int hh = h0 - RAD; hh < h0 + RAD; hh++)
        if (hh >= 0 && hh < HH) s = f4add(s, __ldg(src4 + hh * W4 + w4));

    int h = h0;
    for (int g = 0; g < HCHUNK / 4; g++) {
        float4 a[4], b[4];
        #pragma unroll
        for (int k = 0; k < 4; k++) {
            int hp = h + k + RAD;
            a[k] = (hp < HH) ? __ldg(src4 + hp * W4 + w4) : z4;
            int hm = h + k - RAD;
            b[k] = (hm >= 0) ? __ldg(src4 + hm * W4 + w4) : z4;
        }
        #pragma unroll
        for (int k = 0; k < 4; k++) {
            s = f4add(s, a[k]);
            dst4[(h + k) * W4 + w4] = s;
            s = f4sub(s, b[k]);
        }
        h += 4;
    }
}

// ---------------- pass 3: sliding box sum along D + NCC + reduction ---------
__device__ __forceinline__ float ncc_cc(float Is, float Js, float I2s,
                                        float J2s, float IJs) {
    float uI = Is * INV_WSIZE;
    float uJ = Js * INV_WSIZE;
    float cross = IJs - uJ * Is - uI * Js + uI * uJ * WSIZE;
    float Iv = I2s - 2.f * uI * Is + uI * uI * WSIZE;
    float Jv = J2s - 2.f * uJ * Js + uJ * uJ * WSIZE;
    return cross * cross / (Iv * Jv + 1e-5f);
}

// thread = one (h, w4) column of one pair, 1/5 of the d-range.
// total threads = 3 * 5 * HH * W4 = 115200 -> 450 blocks x 256
#define DCHUNK 32
__global__ __launch_bounds__(256) void k_pass_d() {
    int tid = blockIdx.x * 256 + threadIdx.x;
    int w4 = tid % W4;  tid /= W4;
    int h  = tid % HH;  tid /= HH;
    int dc = tid % 5;   tid /= 5;
    int pair = tid;
    if (pair >= 3) return;

    const float4* __restrict__ ch[5];
    #pragma unroll
    for (int c = 0; c < 5; c++)
        ch[c] = (const float4*)(g_s2 + (size_t)(pair * 5 + c) * VOL);

    const int poff = h * W4 + w4;        // offset within a plane (float4 units)
    const int pstride = HH * W4;         // plane stride (float4 units)
    const float4 z4 = make_float4(0.f, 0.f, 0.f, 0.f);

    int d0 = dc * DCHUNK;
    float4 s[5];
    #pragma unroll
    for (int c = 0; c < 5; c++) s[c] = z4;
    for (int dd = d0 - RAD; dd < d0 + RAD; dd++) {
        if (dd >= 0 && dd < DD) {
            #pragma unroll
            for (int c = 0; c < 5; c++)
                s[c] = f4add(s[c], __ldg(ch[c] + dd * pstride + poff));
        }
    }

    double local = 0.0;
    for (int d = d0; d < d0 + DCHUNK; d++) {
        float4 na[5], ob[5];
        int dp = d + RAD, dm = d - RAD;
        #pragma unroll
        for (int c = 0; c < 5; c++)
            na[c] = (dp < DD) ? __ldg(ch[c] + dp * pstride + poff) : z4;
        #pragma unroll
        for (int c = 0; c < 5; c++)
            ob[c] = (dm >= 0) ? __ldg(ch[c] + dm * pstride + poff) : z4;
        #pragma unroll
        for (int c = 0; c < 5; c++) s[c] = f4add(s[c], na[c]);

        float cx = ncc_cc(s[0].x, s[1].x, s[2].x, s[3].x, s[4].x);
        float cy = ncc_cc(s[0].y, s[1].y, s[2].y, s[3].y, s[4].y);
        float cz = ncc_cc(s[0].z, s[1].z, s[2].z, s[3].z, s[4].z);
        float cw = ncc_cc(s[0].w, s[1].w, s[2].w, s[3].w, s[4].w);
        local += (double)((cx + cy) + (cz + cw));

        #pragma unroll
        for (int c = 0; c < 5; c++) s[c] = f4sub(s[c], ob[c]);
    }

    // warp + block reduce, then atomic per pair (block is single-pair)
    unsigned mask = 0xFFFFFFFFu;
    #pragma unroll
    for (int off = 16; off > 0; off >>= 1)
        local += __shfl_down_sync(mask, local, off);

    __shared__ double red[8];
    int lane = threadIdx.x & 31, warp = threadIdx.x >> 5;
    if (lane == 0) red[warp] = local;
    __syncthreads();
    if (threadIdx.x == 0) {
        double t = 0.0;
        #pragma unroll
        for (int i = 0; i < 8; i++) t += red[i];
        atomicAdd(&g_acc[pair], t);
    }
}

// ---------------- final combine ---------------------------------------------
__global__ void k_final(float* out) {
    double m = (0.8 * g_acc[0] + 0.1 * g_acc[1] + 0.1 * g_acc[2]) / (double)VOL;
    out[0] = (float)(-m);
}

// ---------------- launch ----------------------------------------------------
extern "C" void kernel_launch(void* const* d_in, const int* in_sizes, int n_in,
                              void* d_out, int out_size) {
    const float* I = (const float*)d_in[0];  // y_true
    const float* J = (const float*)d_in[1];  // y_pred
    float* out = (float*)d_out;

    k_zero_acc<<<1, 32>>>();

    dim3 gridHD(HH, DD);
    k_fusedw<<<gridHD, WW>>>(I, J);

    int nthreads_h = NCH * DD * 2 * W4;      // 192000
    k_pass_h<<<nthreads_h / 256, 256>>>();

    int nthreads_d = 3 * 5 * HH * W4;        // 115200
    k_pass_d<<<nthreads_d / 256, 256>>>();

    k_final<<<1, 1>>>(out);
}

// round 8
// speedup vs baseline: 1.9012x; 1.0568x over previous
#include <cuda_runtime.h>
#include <math.h>

// Problem dims: y_true/y_pred shape (1,1,160,192,160) fp32
#define DD 160
#define HH 192
#define WW 160
#define W4 (WW/4)               // 40 float4 per row
#define VOL (DD*HH*WW)          // 4,915,200
#define RAD 4                   // box window radius (win=9)
#define WSIZE 729.0f
#define INV_WSIZE (1.0f/729.0f)
#define NCH 15                  // 3 pairs x 5 channels (A,B,A2,B2,AB)

// ---------------- scratch (device globals: no allocation allowed) ----------
__device__ float g_s1[(size_t)NCH * VOL];   // after fused deriv+w-pass
__device__ float g_s2[(size_t)NCH * VOL];   // after h-pass
__device__ double g_acc[3];                 // per-pair sum of cc

// ---------------- small float4 helpers --------------------------------------
__device__ __forceinline__ float4 f4add(float4 a, float4 b) {
    return make_float4(a.x+b.x, a.y+b.y, a.z+b.z, a.w+b.w);
}
__device__ __forceinline__ float4 f4sub(float4 a, float4 b) {
    return make_float4(a.x-b.x, a.y-b.y, a.z-b.z, a.w-b.w);
}

// ---------------- accumulator reset ----------------------------------------
__global__ void k_zero_acc() {
    if (threadIdx.x < 3) g_acc[threadIdx.x] = 0.0;
}

// ---------------- 3x3x3 stencils: Laplacian + Sobel magnitude --------------
__device__ __forceinline__ void stencil_eval(const float s[3][3][WW + 2], int cw,
                                             float& lap, float& shp) {
    const float m3[3] = {1.f, 2.f, 1.f};
    float c = s[1][1][cw];
    lap = 6.f * c
        - s[1][1][cw - 1] - s[1][1][cw + 1]
        - s[1][0][cw]     - s[1][2][cw]
        - s[0][1][cw]     - s[2][1][cw];

    float gx = 0.f, gy = 0.f, gz = 0.f;
    #pragma unroll
    for (int dz = 0; dz < 3; dz++)
        #pragma unroll
        for (int dy = 0; dy < 3; dy++)
            gx += m3[dy] * (s[dz][dy][cw + 1] - s[dz][dy][cw - 1]);
    #pragma unroll
    for (int dy = 0; dy < 3; dy++)
        #pragma unroll
        for (int dw = 0; dw < 3; dw++)
            gy += m3[dw] * (s[2][dy][cw + dw - 1] - s[0][dy][cw + dw - 1]);
    #pragma unroll
    for (int dz = 0; dz < 3; dz++)
        #pragma unroll
        for (int dw = 0; dw < 3; dw++)
            gz += m3[dz] * (s[dz][2][cw + dw - 1] - s[dz][0][cw + dw - 1]);

    shp = sqrtf(gx * gx + gy * gy + gz * gz);
}

// ---------------- fused: deriv + products + box-sum along W -----------------
__global__ __launch_bounds__(WW) void k_fusedw(const float* __restrict__ I,
                                               const float* __restrict__ J) {
    __shared__ float sI[3][3][WW + 2];
    __shared__ float sJ[3][3][WW + 2];
    __shared__ float vals[6][WW];  // I, J, eI, eJ, shI, shJ (center row)
    const int h = blockIdx.x;
    const int d = blockIdx.y;
    const int t = threadIdx.x;

    #pragma unroll
    for (int dz = 0; dz < 3; dz++) {
        int dd = d + dz - 1;
        #pragma unroll
        for (int dy = 0; dy < 3; dy++) {
            int hh = h + dy - 1;
            bool rowok = (dd >= 0 && dd < DD && hh >= 0 && hh < HH);
            size_t rb = ((size_t)dd * HH + hh) * WW;
            for (int x = t; x < WW + 2; x += WW) {
                int ws = x - 1;
                float vi = 0.f, vj = 0.f;
                if (rowok && ws >= 0 && ws < WW) {
                    vi = __ldg(I + rb + ws);
                    vj = __ldg(J + rb + ws);
                }
                sI[dz][dy][x] = vi;
                sJ[dz][dy][x] = vj;
            }
        }
    }
    __syncthreads();

    const int cw = t + 1;
    float lapI, shpI, lapJ, shpJ;
    stencil_eval(sI, cw, lapI, shpI);
    stencil_eval(sJ, cw, lapJ, shpJ);
    vals[0][t] = sI[1][1][cw];
    vals[1][t] = sJ[1][1][cw];
    vals[2][t] = lapI;
    vals[3][t] = lapJ;
    vals[4][t] = shpI;
    vals[5][t] = shpJ;
    __syncthreads();

    float acc[NCH];
    #pragma unroll
    for (int c = 0; c < NCH; c++) acc[c] = 0.f;

    #pragma unroll
    for (int dw = -RAD; dw <= RAD; dw++) {
        int x = t + dw;
        if (x >= 0 && x < WW) {
            float a0 = vals[0][x], b0 = vals[1][x];
            float a1 = vals[2][x], b1 = vals[3][x];
            float a2 = vals[4][x], b2 = vals[5][x];
            acc[0] += a0;       acc[1] += b0;
            acc[2] += a0 * a0;  acc[3] += b0 * b0;  acc[4]  += a0 * b0;
            acc[5] += a1;       acc[6] += b1;
            acc[7] += a1 * a1;  acc[8] += b1 * b1;  acc[9]  += a1 * b1;
            acc[10] += a2;      acc[11] += b2;
            acc[12] += a2 * a2; acc[13] += b2 * b2; acc[14] += a2 * b2;
        }
    }

    size_t idx = ((size_t)d * HH + h) * WW + t;
    #pragma unroll
    for (int c = 0; c < NCH; c++)
        g_s1[(size_t)c * VOL + idx] = acc[c];
}

// ---------------- pass 2: sliding-window box sum along H --------------------
// thread = one float4 column of one channel of one d-plane; marches FULL h.
// Full-axis march keeps the trailing (h-4) tap within a tiny L2 reuse window.
// total threads = NCH * DD * W4 = 96000 -> 375 blocks x 256
__global__ __launch_bounds__(256) void k_pass_h() {
    int tid = blockIdx.x * 256 + threadIdx.x;
    int w4 = tid % W4;  tid /= W4;
    int d  = tid % DD;  tid /= DD;
    int c  = tid;
    if (c >= NCH) return;

    size_t base = (size_t)c * VOL + (size_t)d * HH * WW;
    const float4* __restrict__ src4 = (const float4*)(g_s1 + base);
    float4* __restrict__ dst4 = (float4*)(g_s2 + base);
    const float4 z4 = make_float4(0.f, 0.f, 0.f, 0.f);

    float4 s = z4;
    #pragma unroll
    for (int hh = 0; hh < RAD; hh++)
        s = f4add(s, __ldg(src4 + hh * W4 + w4));

    int h = 0;
    #pragma unroll 1
    for (int g = 0; g < HH / 4; g++) {
        float4 a[4], b[4];
        #pragma unroll
        for (int k = 0; k < 4; k++) {
            int hp = h + k + RAD;
            a[k] = (hp < HH) ? __ldg(src4 + hp * W4 + w4) : z4;
            int hm = h + k - RAD;
            b[k] = (hm >= 0) ? __ldg(src4 + hm * W4 + w4) : z4;
        }
        #pragma unroll
        for (int k = 0; k < 4; k++) {
            s = f4add(s, a[k]);
            dst4[(h + k) * W4 + w4] = s;
            s = f4sub(s, b[k]);
        }
        h += 4;
    }
}

// ---------------- pass 3: sliding box sum along D + NCC + reduction ---------
__device__ __forceinline__ float ncc_cc(float Is, float Js, float I2s,
                                        float J2s, float IJs) {
    float uI = Is * INV_WSIZE;
    float uJ = Js * INV_WSIZE;
    float cross = IJs - uJ * Is - uI * Js + uI * uJ * WSIZE;
    float Iv = I2s - 2.f * uI * Is + uI * uI * WSIZE;
    float Jv = J2s - 2.f * uJ * Js + uJ * uJ * WSIZE;
    return cross * cross / (Iv * Jv + 1e-5f);
}

// thread = one (h, w4) column of one pair; marches the FULL d range so the
// trailing (d-4) plane tap is an L2 hit (reuse window ~15MB << 126MB L2).
// total threads = 3 * HH * W4 = 23040 -> 180 blocks x 128
__global__ __launch_bounds__(128) void k_pass_d() {
    int tid = blockIdx.x * 128 + threadIdx.x;
    int w4 = tid % W4;  tid /= W4;
    int h  = tid % HH;  tid /= HH;
    int pair = tid;
    if (pair >= 3) return;

    const float4* __restrict__ ch[5];
    #pragma unroll
    for (int c = 0; c < 5; c++)
        ch[c] = (const float4*)(g_s2 + (size_t)(pair * 5 + c) * VOL);

    const int poff = h * W4 + w4;        // offset within a plane (float4 units)
    const int pstride = HH * W4;         // plane stride (float4 units)
    const float4 z4 = make_float4(0.f, 0.f, 0.f, 0.f);

    float4 s[5];
    #pragma unroll
    for (int c = 0; c < 5; c++) s[c] = z4;
    #pragma unroll
    for (int dd = 0; dd < RAD; dd++) {
        #pragma unroll
        for (int c = 0; c < 5; c++)
            s[c] = f4add(s[c], __ldg(ch[c] + dd * pstride + poff));
    }

    double local = 0.0;
    #pragma unroll 2
    for (int d = 0; d < DD; d++) {
        float4 na[5], ob[5];
        int dp = d + RAD, dm = d - RAD;
        #pragma unroll
        for (int c = 0; c < 5; c++)
            na[c] = (dp < DD) ? __ldg(ch[c] + dp * pstride + poff) : z4;
        #pragma unroll
        for (int c = 0; c < 5; c++)
            ob[c] = (dm >= 0) ? __ldg(ch[c] + dm * pstride + poff) : z4;
        #pragma unroll
        for (int c = 0; c < 5; c++) s[c] = f4add(s[c], na[c]);

        float cx = ncc_cc(s[0].x, s[1].x, s[2].x, s[3].x, s[4].x);
        float cy = ncc_cc(s[0].y, s[1].y, s[2].y, s[3].y, s[4].y);
        float cz = ncc_cc(s[0].z, s[1].z, s[2].z, s[3].z, s[4].z);
        float cw = ncc_cc(s[0].w, s[1].w, s[2].w, s[3].w, s[4].w);
        local += (double)((cx + cy) + (cz + cw));

        #pragma unroll
        for (int c = 0; c < 5; c++) s[c] = f4sub(s[c], ob[c]);
    }

    // warp + block reduce, then atomic per pair (block is single-pair)
    unsigned mask = 0xFFFFFFFFu;
    #pragma unroll
    for (int off = 16; off > 0; off >>= 1)
        local += __shfl_down_sync(mask, local, off);

    __shared__ double red[4];
    int lane = threadIdx.x & 31, warp = threadIdx.x >> 5;
    if (lane == 0) red[warp] = local;
    __syncthreads();
    if (threadIdx.x == 0) {
        double t = red[0] + red[1] + red[2] + red[3];
        atomicAdd(&g_acc[pair], t);
    }
}

// ---------------- final combine ---------------------------------------------
__global__ void k_final(float* out) {
    double m = (0.8 * g_acc[0] + 0.1 * g_acc[1] + 0.1 * g_acc[2]) / (double)VOL;
    out[0] = (float)(-m);
}

// ---------------- launch ----------------------------------------------------
extern "C" void kernel_launch(void* const* d_in, const int* in_sizes, int n_in,
                              void* d_out, int out_size) {
    const float* I = (const float*)d_in[0];  // y_true
    const float* J = (const float*)d_in[1];  // y_pred
    float* out = (float*)d_out;

    k_zero_acc<<<1, 32>>>();

    dim3 gridHD(HH, DD);
    k_fusedw<<<gridHD, WW>>>(I, J);

    int nthreads_h = NCH * DD * W4;          // 96000
    k_pass_h<<<nthreads_h / 256, 256>>>();

    int nthreads_d = 3 * HH * W4;            // 23040
    k_pass_d<<<nthreads_d / 128, 128>>>();

    k_final<<<1, 1>>>(out);
}

// round 9
// speedup vs baseline: 2.1834x; 1.1485x over previous
#include <cuda_runtime.h>
#include <math.h>

// Problem dims: y_true/y_pred shape (1,1,160,192,160) fp32
#define DD 160
#define HH 192
#define WW 160
#define W4 (WW/4)               // 40 float4 per row
#define VOL (DD*HH*WW)          // 4,915,200
#define VOL4 (VOL/4)
#define RAD 4                   // box window radius (win=9)
#define WSIZE 729.0f
#define INV_WSIZE (1.0f/729.0f)
#define NCH 15                  // 3 pairs x 5 channels (A,B,A2,B2,AB)
#define DCH 80                  // d-planes per thread chunk (2 chunks)

// ---------------- scratch (device globals: no allocation allowed) ----------
__device__ float g_s1[(size_t)NCH * VOL];   // after fused deriv+w-pass
__device__ double g_acc[3];                 // per-pair sum of cc

// ---------------- small float4 helpers --------------------------------------
__device__ __forceinline__ float4 f4add(float4 a, float4 b) {
    return make_float4(a.x+b.x, a.y+b.y, a.z+b.z, a.w+b.w);
}
__device__ __forceinline__ float4 f4sub(float4 a, float4 b) {
    return make_float4(a.x-b.x, a.y-b.y, a.z-b.z, a.w-b.w);
}

// ---------------- accumulator reset ----------------------------------------
__global__ void k_zero_acc() {
    if (threadIdx.x < 3) g_acc[threadIdx.x] = 0.0;
}

// ---------------- 3x3x3 stencils: Laplacian + Sobel magnitude --------------
__device__ __forceinline__ void stencil_eval(const float s[3][3][WW + 2], int cw,
                                             float& lap, float& shp) {
    const float m3[3] = {1.f, 2.f, 1.f};
    float c = s[1][1][cw];
    lap = 6.f * c
        - s[1][1][cw - 1] - s[1][1][cw + 1]
        - s[1][0][cw]     - s[1][2][cw]
        - s[0][1][cw]     - s[2][1][cw];

    float gx = 0.f, gy = 0.f, gz = 0.f;
    #pragma unroll
    for (int dz = 0; dz < 3; dz++)
        #pragma unroll
        for (int dy = 0; dy < 3; dy++)
            gx += m3[dy] * (s[dz][dy][cw + 1] - s[dz][dy][cw - 1]);
    #pragma unroll
    for (int dy = 0; dy < 3; dy++)
        #pragma unroll
        for (int dw = 0; dw < 3; dw++)
            gy += m3[dw] * (s[2][dy][cw + dw - 1] - s[0][dy][cw + dw - 1]);
    #pragma unroll
    for (int dz = 0; dz < 3; dz++)
        #pragma unroll
        for (int dw = 0; dw < 3; dw++)
            gz += m3[dz] * (s[dz][2][cw + dw - 1] - s[dz][0][cw + dw - 1]);

    shp = sqrtf(gx * gx + gy * gy + gz * gz);
}

// ---------------- fused: deriv + products + box-sum along W -----------------
__global__ __launch_bounds__(WW) void k_fusedw(const float* __restrict__ I,
                                               const float* __restrict__ J) {
    __shared__ float sI[3][3][WW + 2];
    __shared__ float sJ[3][3][WW + 2];
    __shared__ float vals[6][WW];  // I, J, eI, eJ, shI, shJ (center row)
    const int h = blockIdx.x;
    const int d = blockIdx.y;
    const int t = threadIdx.x;

    #pragma unroll
    for (int dz = 0; dz < 3; dz++) {
        int dd = d + dz - 1;
        #pragma unroll
        for (int dy = 0; dy < 3; dy++) {
            int hh = h + dy - 1;
            bool rowok = (dd >= 0 && dd < DD && hh >= 0 && hh < HH);
            size_t rb = ((size_t)dd * HH + hh) * WW;
            for (int x = t; x < WW + 2; x += WW) {
                int ws = x - 1;
                float vi = 0.f, vj = 0.f;
                if (rowok && ws >= 0 && ws < WW) {
                    vi = __ldg(I + rb + ws);
                    vj = __ldg(J + rb + ws);
                }
                sI[dz][dy][x] = vi;
                sJ[dz][dy][x] = vj;
            }
        }
    }
    __syncthreads();

    const int cw = t + 1;
    float lapI, shpI, lapJ, shpJ;
    stencil_eval(sI, cw, lapI, shpI);
    stencil_eval(sJ, cw, lapJ, shpJ);
    vals[0][t] = sI[1][1][cw];
    vals[1][t] = sJ[1][1][cw];
    vals[2][t] = lapI;
    vals[3][t] = lapJ;
    vals[4][t] = shpI;
    vals[5][t] = shpJ;
    __syncthreads();

    float acc[NCH];
    #pragma unroll
    for (int c = 0; c < NCH; c++) acc[c] = 0.f;

    #pragma unroll
    for (int dw = -RAD; dw <= RAD; dw++) {
        int x = t + dw;
        if (x >= 0 && x < WW) {
            float a0 = vals[0][x], b0 = vals[1][x];
            float a1 = vals[2][x], b1 = vals[3][x];
            float a2 = vals[4][x], b2 = vals[5][x];
            acc[0] += a0;       acc[1] += b0;
            acc[2] += a0 * a0;  acc[3] += b0 * b0;  acc[4]  += a0 * b0;
            acc[5] += a1;       acc[6] += b1;
            acc[7] += a1 * a1;  acc[8] += b1 * b1;  acc[9]  += a1 * b1;
            acc[10] += a2;      acc[11] += b2;
            acc[12] += a2 * a2; acc[13] += b2 * b2; acc[14] += a2 * b2;
        }
    }

    size_t idx = ((size_t)d * HH + h) * WW + t;
    #pragma unroll
    for (int c = 0; c < NCH; c++)
        g_s1[(size_t)c * VOL + idx] = acc[c];
}

// ---------------- NCC formula ----------------------------------------------
__device__ __forceinline__ float ncc_cc(float Is, float Js, float I2s,
                                        float J2s, float IJs) {
    float uI = Is * INV_WSIZE;
    float uJ = Js * INV_WSIZE;
    float cross = IJs - uJ * Is - uI * Js + uI * uJ * WSIZE;
    float Iv = I2s - 2.f * uI * Is + uI * uI * WSIZE;
    float Jv = J2s - 2.f * uJ * Js + uJ * uJ * WSIZE;
    return cross * cross / (Iv * Jv + 1e-5f);
}

// ---------------- fused pass: h-box + d-box + NCC + reduction ---------------
// thread = one (pair, h, w4) column, marches DCH d-planes.
// Per step: compute h-box of plane d+RAD with 9 h-taps x 5 ch (L1-shared
// across neighboring-h threads), slide the d-window using a per-thread
// 8-slot local-memory ring for the outgoing plane's h-box.
// threads = 3 * 2 * HH * W4 = 46080 -> 360 blocks x 128
__global__ __launch_bounds__(128) void k_pass_hd() {
    int tid = blockIdx.x * 128 + threadIdx.x;
    int w4 = tid % W4;  tid /= W4;
    int h  = tid % HH;  tid /= HH;
    int dc = tid % 2;   tid /= 2;
    int pair = tid;
    if (pair >= 3) return;

    const float4* __restrict__ ch[5];
    #pragma unroll
    for (int c = 0; c < 5; c++)
        ch[c] = (const float4*)g_s1 + (size_t)(pair * 5 + c) * VOL4;

    const int h0 = (h - RAD < 0) ? 0 : h - RAD;
    const int h1 = (h + RAD > HH - 1) ? HH - 1 : h + RAD;
    const int pstride = HH * W4;  // plane stride in float4

    float4 ring[8][5];            // local-memory ring (dynamic index)
    float4 S[5];
    const float4 z4 = make_float4(0.f, 0.f, 0.f, 0.f);
    #pragma unroll
    for (int c = 0; c < 5; c++) S[c] = z4;

    const int d0 = dc * DCH;

    // warmup: h-box of planes [d0-RAD, d0+RAD) into ring + running sum
    for (int dd = d0 - RAD; dd < d0 + RAD; dd++) {
        if (dd < 0 || dd >= DD) continue;
        float4 hb[5];
        #pragma unroll
        for (int c = 0; c < 5; c++) hb[c] = z4;
        for (int hh = h0; hh <= h1; hh++) {
            int off = dd * pstride + hh * W4 + w4;
            #pragma unroll
            for (int c = 0; c < 5; c++)
                hb[c] = f4add(hb[c], __ldg(ch[c] + off));
        }
        int slot = dd & 7;
        #pragma unroll
        for (int c = 0; c < 5; c++) {
            ring[slot][c] = hb[c];
            S[c] = f4add(S[c], hb[c]);
        }
    }

    double local = 0.0;
    #pragma unroll 1
    for (int d = d0; d < d0 + DCH; d++) {
        // fetch outgoing h-box BEFORE its slot is overwritten
        const bool hasOld = (d - RAD) >= 0;
        float4 old[5];
        if (hasOld) {
            int oslot = (d - RAD) & 7;
            #pragma unroll
            for (int c = 0; c < 5; c++) old[c] = ring[oslot][c];
        }

        const int dp = d + RAD;
        if (dp < DD) {
            float4 hb[5];
            #pragma unroll
            for (int c = 0; c < 5; c++) hb[c] = z4;
            for (int hh = h0; hh <= h1; hh++) {
                int off = dp * pstride + hh * W4 + w4;
                #pragma unroll
                for (int c = 0; c < 5; c++)
                    hb[c] = f4add(hb[c], __ldg(ch[c] + off));
            }
            int nslot = dp & 7;
            #pragma unroll
            for (int c = 0; c < 5; c++) {
                ring[nslot][c] = hb[c];
                S[c] = f4add(S[c], hb[c]);
            }
        }

        float cx = ncc_cc(S[0].x, S[1].x, S[2].x, S[3].x, S[4].x);
        float cy = ncc_cc(S[0].y, S[1].y, S[2].y, S[3].y, S[4].y);
        float cz = ncc_cc(S[0].z, S[1].z, S[2].z, S[3].z, S[4].z);
        float cw = ncc_cc(S[0].w, S[1].w, S[2].w, S[3].w, S[4].w);
        local += (double)((cx + cy) + (cz + cw));

        if (hasOld) {
            #pragma unroll
            for (int c = 0; c < 5; c++) S[c] = f4sub(S[c], old[c]);
        }
    }

    // warp + block reduce, then one atomic per block (block is single-pair)
    unsigned mask = 0xFFFFFFFFu;
    #pragma unroll
    for (int off = 16; off > 0; off >>= 1)
        local += __shfl_down_sync(mask, local, off);

    __shared__ double red[4];
    int lane = threadIdx.x & 31, warp = threadIdx.x >> 5;
    if (lane == 0) red[warp] = local;
    __syncthreads();
    if (threadIdx.x == 0) {
        double t = red[0] + red[1] + red[2] + red[3];
        atomicAdd(&g_acc[pair], t);
    }
}

// ---------------- final combine ---------------------------------------------
__global__ void k_final(float* out) {
    double m = (0.8 * g_acc[0] + 0.1 * g_acc[1] + 0.1 * g_acc[2]) / (double)VOL;
    out[0] = (float)(-m);
}

// ---------------- launch ----------------------------------------------------
extern "C" void kernel_launch(void* const* d_in, const int* in_sizes, int n_in,
                              void* d_out, int out_size) {
    const float* I = (const float*)d_in[0];  // y_true
    const float* J = (const float*)d_in[1];  // y_pred
    float* out = (float*)d_out;

    k_zero_acc<<<1, 32>>>();

    dim3 gridHD(HH, DD);
    k_fusedw<<<gridHD, WW>>>(I, J);

    int nthreads_hd = 3 * 2 * HH * W4;       // 46080
    k_pass_hd<<<nthreads_hd / 128, 128>>>();

    k_final<<<1, 1>>>(out);
}

// round 10
// speedup vs baseline: 2.2101x; 1.0122x over previous
#include <cuda_runtime.h>
#include <math.h>

// Problem dims: y_true/y_pred shape (1,1,160,192,160) fp32
#define DD 160
#define HH 192
#define WW 160
#define W4 (WW/4)               // 40 float4 per row
#define VOL (DD*HH*WW)          // 4,915,200
#define VOL4 (VOL/4)
#define RAD 4                   // box window radius (win=9)
#define WSIZE 729.0f
#define INV_WSIZE (1.0f/729.0f)
#define NCH 15                  // 3 pairs x 5 channels (A,B,A2,B2,AB)
#define HCHB 48                 // output h-rows per fusedwh block (4 chunks)
#define DCH2 40                 // d-planes per pass_d thread (4 chunks)

// ---------------- scratch (device globals: no allocation allowed) ----------
__device__ float g_s1[(size_t)NCH * VOL];   // h∘w-boxed product channels
__device__ double g_acc[3];                 // per-pair sum of cc

// ---------------- small float4 helpers --------------------------------------
__device__ __forceinline__ float4 f4add(float4 a, float4 b) {
    return make_float4(a.x+b.x, a.y+b.y, a.z+b.z, a.w+b.w);
}
__device__ __forceinline__ float4 f4sub(float4 a, float4 b) {
    return make_float4(a.x-b.x, a.y-b.y, a.z-b.z, a.w-b.w);
}

// ---------------- accumulator reset ----------------------------------------
__global__ void k_zero_acc() {
    if (threadIdx.x < 3) g_acc[threadIdx.x] = 0.0;
}

// ---------------- 3x3x3 stencils on h-slot ring smem ------------------------
// sm[hslot][dz][x]: hslot = row index mod 3 (y0=row r-1, y1=row r, y2=row r+1)
__device__ __forceinline__ void stencil_rows(const float sm[3][3][WW + 2],
                                             int y0, int y1, int y2, int cw,
                                             float& lap, float& shp) {
    int ys[3] = {y0, y1, y2};
    const float m3[3] = {1.f, 2.f, 1.f};
    float c = sm[y1][1][cw];
    lap = 6.f * c
        - sm[y1][1][cw - 1] - sm[y1][1][cw + 1]   // w +/- 1
        - sm[y0][1][cw]     - sm[y2][1][cw]       // h +/- 1
        - sm[y1][0][cw]     - sm[y1][2][cw];      // d +/- 1

    float gx = 0.f, gy = 0.f, gz = 0.f;
    #pragma unroll
    for (int dz = 0; dz < 3; dz++)
        #pragma unroll
        for (int dy = 0; dy < 3; dy++)
            gx += m3[dy] * (sm[ys[dy]][dz][cw + 1] - sm[ys[dy]][dz][cw - 1]);
    #pragma unroll
    for (int dy = 0; dy < 3; dy++)
        #pragma unroll
        for (int dw = 0; dw < 3; dw++)
            gy += m3[dw] * (sm[ys[dy]][2][cw + dw - 1] - sm[ys[dy]][0][cw + dw - 1]);
    #pragma unroll
    for (int dz = 0; dz < 3; dz++)
        #pragma unroll
        for (int dw = 0; dw < 3; dw++)
            gz += m3[dz] * (sm[y2][dz][cw + dw - 1] - sm[y0][dz][cw + dw - 1]);

    shp = sqrtf(gx * gx + gy * gy + gz * gz);
}

// load input row r (3 d-planes x 2 vols) into h-slot ring
__device__ __forceinline__ void load_row(float (*sA)[3][WW + 2],
                                         float (*sB)[3][WW + 2],
                                         const float* __restrict__ I,
                                         const float* __restrict__ J,
                                         int d, int r, int t) {
    int slot = (r + 9) % 3;
    #pragma unroll
    for (int dz = 0; dz < 3; dz++) {
        int dd = d + dz - 1;
        bool rok = (dd >= 0 && dd < DD && r >= 0 && r < HH);
        size_t rb = ((size_t)dd * HH + r) * WW;
        #pragma unroll
        for (int ii = 0; ii < 2; ii++) {
            int idx = t + ii * WW;
            if (idx < WW + 2) {
                int w = idx - 1;
                float vi = 0.f, vj = 0.f;
                if (rok && w >= 0 && w < WW) {
                    vi = __ldg(I + rb + w);
                    vj = __ldg(J + rb + w);
                }
                sA[slot][dz][idx] = vi;
                sB[slot][dz][idx] = vj;
            }
        }
    }
}

// ---------------- fused: deriv + products + w-box + sliding h-box -----------
// block = (d, h-chunk), 160 threads (one per w), marches h through its chunk.
// Writes g_s1 = h-box( w-box( products ) ) for all 15 channels.
__global__ __launch_bounds__(WW) void k_fusedwh(const float* __restrict__ I,
                                                const float* __restrict__ J) {
    __shared__ float sA[3][3][WW + 2];   // [hslot][dz][w+1] for I
    __shared__ float sB[3][3][WW + 2];   // for J
    __shared__ float vals[6][WW + 8];    // zero-padded base-value row
    const int d  = blockIdx.x;
    const int h0 = blockIdx.y * HCHB;
    const int t  = threadIdx.x;

    // zero w-halo pads of vals (written once, never touched again)
    if (t < 4) {
        #pragma unroll
        for (int c = 0; c < 6; c++) {
            vals[c][t] = 0.f;
            vals[c][WW + 4 + t] = 0.f;
        }
    }

    float ring[16][NCH];    // local-mem ring of w-boxed product rows
    float S[NCH];
    #pragma unroll
    for (int c = 0; c < NCH; c++) S[c] = 0.f;

    const int s_begin = h0 - 2 * RAD;
    // prefill input rows s_begin+3, s_begin+4
    load_row(sA, sB, I, J, d, s_begin + 3, t);
    load_row(sA, sB, I, J, d, s_begin + 4, t);
    __syncthreads();

    #pragma unroll 1
    for (int s = s_begin; s < h0 + HCHB; s++) {
        load_row(sA, sB, I, J, d, s + 5, t);
        __syncthreads();

        const int r = s + RAD;              // incoming product row
        const bool addok = (r >= 0 && r < HH);
        if (addok) {
            int y0 = (r - 1 + 9) % 3, y1 = (r + 9) % 3, y2 = (r + 1 + 9) % 3;
            float lapI, shpI, lapJ, shpJ;
            stencil_rows(sA, y0, y1, y2, t + 1, lapI, shpI);
            stencil_rows(sB, y0, y1, y2, t + 1, lapJ, shpJ);
            vals[0][t + 4] = sA[y1][1][t + 1];
            vals[1][t + 4] = sB[y1][1][t + 1];
            vals[2][t + 4] = lapI;
            vals[3][t + 4] = lapJ;
            vals[4][t + 4] = shpI;
            vals[5][t + 4] = shpJ;
        }
        __syncthreads();

        if (addok) {
            float hb[NCH];
            #pragma unroll
            for (int c = 0; c < NCH; c++) hb[c] = 0.f;
            #pragma unroll
            for (int dx = -RAD; dx <= RAD; dx++) {
                int x = t + 4 + dx;          // always in-range (zero-padded)
                float a0 = vals[0][x], b0 = vals[1][x];
                float a1 = vals[2][x], b1 = vals[3][x];
                float a2 = vals[4][x], b2 = vals[5][x];
                hb[0] += a0;       hb[1] += b0;
                hb[2] += a0 * a0;  hb[3] += b0 * b0;  hb[4]  += a0 * b0;
                hb[5] += a1;       hb[6] += b1;
                hb[7] += a1 * a1;  hb[8] += b1 * b1;  hb[9]  += a1 * b1;
                hb[10] += a2;      hb[11] += b2;
                hb[12] += a2 * a2; hb[13] += b2 * b2; hb[14] += a2 * b2;
            }
            int slot = r & 15;
            #pragma unroll
            for (int c = 0; c < NCH; c++) {
                ring[slot][c] = hb[c];
                S[c] += hb[c];
            }
        }

        // drop row s-5 (only if it was added by this block and is valid)
        const int q = s - RAD - 1;
        if (q >= 0 && q >= h0 - RAD) {
            int qs = q & 15;
            #pragma unroll
            for (int c = 0; c < NCH; c++) S[c] -= ring[qs][c];
        }

        // write h-box(s) = rows [s-4, s+4] clamped
        if (s >= h0) {
            size_t idx = ((size_t)d * HH + s) * WW + t;
            #pragma unroll
            for (int c = 0; c < NCH; c++)
                g_s1[(size_t)c * VOL + idx] = S[c];
        }
    }
}

// ---------------- NCC formula ----------------------------------------------
__device__ __forceinline__ float ncc_cc(float Is, float Js, float I2s,
                                        float J2s, float IJs) {
    float uI = Is * INV_WSIZE;
    float uJ = Js * INV_WSIZE;
    float cross = IJs - uJ * Is - uI * Js + uI * uJ * WSIZE;
    float Iv = I2s - 2.f * uI * Is + uI * uI * WSIZE;
    float Jv = J2s - 2.f * uJ * Js + uJ * uJ * WSIZE;
    return cross * cross / (Iv * Jv + 1e-5f);
}

// ---------------- pass: sliding d-box of boxed planes + NCC + reduction -----
// g_s1 rows are already h∘w-boxed: 5 LDG.128 per step + 8-slot d-ring.
// threads = 3 * 4 * HH * W4 = 92160 -> 720 blocks x 128
__global__ __launch_bounds__(128) void k_pass_d() {
    int tid = blockIdx.x * 128 + threadIdx.x;
    int w4 = tid % W4;  tid /= W4;
    int h  = tid % HH;  tid /= HH;
    int dc = tid % 4;   tid /= 4;
    int pair = tid;
    if (pair >= 3) return;

    const float4* __restrict__ ch[5];
    #pragma unroll
    for (int c = 0; c < 5; c++)
        ch[c] = (const float4*)g_s1 + (size_t)(pair * 5 + c) * VOL4;

    const int poff = h * W4 + w4;
    const int pstride = HH * W4;
    const float4 z4 = make_float4(0.f, 0.f, 0.f, 0.f);

    float4 ring[8][5];
    float4 S[5];
    #pragma unroll
    for (int c = 0; c < 5; c++) S[c] = z4;

    const int d0 = dc * DCH2;

    // warmup: planes [d0-4, d0+4)
    for (int dd = d0 - RAD; dd < d0 + RAD; dd++) {
        if (dd < 0 || dd >= DD) continue;
        int slot = dd & 7;
        #pragma unroll
        for (int c = 0; c < 5; c++) {
            float4 v = __ldg(ch[c] + dd * pstride + poff);
            ring[slot][c] = v;
            S[c] = f4add(S[c], v);
        }
    }

    double local = 0.0;
    #pragma unroll 2
    for (int d = d0; d < d0 + DCH2; d++) {
        const bool hasOld = (d - RAD) >= 0;
        float4 old[5];
        if (hasOld) {
            int oslot = (d - RAD) & 7;
            #pragma unroll
            for (int c = 0; c < 5; c++) old[c] = ring[oslot][c];
        }

        const int dp = d + RAD;
        if (dp < DD) {
            int nslot = dp & 7;
            #pragma unroll
            for (int c = 0; c < 5; c++) {
                float4 v = __ldg(ch[c] + dp * pstride + poff);
                ring[nslot][c] = v;
                S[c] = f4add(S[c], v);
            }
        }

        float cx = ncc_cc(S[0].x, S[1].x, S[2].x, S[3].x, S[4].x);
        float cy = ncc_cc(S[0].y, S[1].y, S[2].y, S[3].y, S[4].y);
        float cz = ncc_cc(S[0].z, S[1].z, S[2].z, S[3].z, S[4].z);
        float cw = ncc_cc(S[0].w, S[1].w, S[2].w, S[3].w, S[4].w);
        local += (double)((cx + cy) + (cz + cw));

        if (hasOld) {
            #pragma unroll
            for (int c = 0; c < 5; c++) S[c] = f4sub(S[c], old[c]);
        }
    }

    // warp + block reduce, one atomic per block (block is single-pair)
    unsigned mask = 0xFFFFFFFFu;
    #pragma unroll
    for (int off = 16; off > 0; off >>= 1)
        local += __shfl_down_sync(mask, local, off);

    __shared__ double red[4];
    int lane = threadIdx.x & 31, warp = threadIdx.x >> 5;
    if (lane == 0) red[warp] = local;
    __syncthreads();
    if (threadIdx.x == 0) {
        double tsum = red[0] + red[1] + red[2] + red[3];
        atomicAdd(&g_acc[pair], tsum);
    }
}

// ---------------- final combine ---------------------------------------------
__global__ void k_final(float* out) {
    double m = (0.8 * g_acc[0] + 0.1 * g_acc[1] + 0.1 * g_acc[2]) / (double)VOL;
    out[0] = (float)(-m);
}

// ---------------- launch ----------------------------------------------------
extern "C" void kernel_launch(void* const* d_in, const int* in_sizes, int n_in,
                              void* d_out, int out_size) {
    const float* I = (const float*)d_in[0];  // y_true
    const float* J = (const float*)d_in[1];  // y_pred
    float* out = (float*)d_out;

    k_zero_acc<<<1, 32>>>();

    dim3 gridF(DD, HH / HCHB);               // 160 x 4 = 640 blocks
    k_fusedwh<<<gridF, WW>>>(I, J);

    int nthreads_d = 3 * 4 * HH * W4;        // 92160
    k_pass_d<<<nthreads_d / 128, 128>>>();

    k_final<<<1, 1>>>(out);
}